// round 12
// baseline (speedup 1.0000x reference)
#include <cuda_runtime.h>
#include <cstdint>

#define N_NODES   50000
#define IN_FEAT   128
#define OUT_FEAT  128
#define NB        16
#define SI        8
#define SO        8
#define W_PER_REL (NB * SI * SO)   // 1024
#define E_MAX     500000
#define MAXR      200
#define NBLK2     464               // sort blocks (2 waves-ish for scatter parallelism)
#define SORT_TPB  256
#define EPW       16                // edges per warp in edge kernel
#define GM_ROWS   64

// Scratch (static device globals — allocation-free per harness rules)
__device__ int4 g_edges[E_MAX];            // (src, dst, etype, norm_bits), etype-sorted
__device__ int  g_bh[MAXR * NBLK2];        // per-(rel, block) counts -> base offsets

// ---------------------------------------------------------------------------
__device__ __forceinline__ void red_add_v4(float* addr, float4 v) {
    asm volatile("red.global.add.v4.f32 [%0], {%1, %2, %3, %4};"
                 :: "l"(addr), "f"(v.x), "f"(v.y), "f"(v.z), "f"(v.w)
                 : "memory");
}

// ---------------------------------------------------------------------------
// Sort pass 1: per-block histogram over contiguous edge chunk (grid = NBLK2)
// Also zeroes d_out so the edge kernel can RED directly into it.
// ---------------------------------------------------------------------------
__global__ __launch_bounds__(SORT_TPB) void k_hist(const int* __restrict__ et,
                                                   float* __restrict__ out,
                                                   int n, int chunk) {
    __shared__ int sh[MAXR];
    int tid = threadIdx.x, bid = blockIdx.x;
    if (tid < MAXR) sh[tid] = 0;
    __syncthreads();

    // zero d_out (grid-stride float4)
    {
        float4* out4 = reinterpret_cast<float4*>(out);
        int total4 = N_NODES * OUT_FEAT / 4;
        for (int i = bid * SORT_TPB + tid; i < total4; i += NBLK2 * SORT_TPB)
            out4[i] = make_float4(0.f, 0.f, 0.f, 0.f);
    }

    int lo = bid * chunk;
    int hi = lo + chunk; if (hi > n) hi = n;
    for (int e = lo + tid; e < hi; e += SORT_TPB)
        atomicAdd(&sh[et[e]], 1);
    __syncthreads();
    if (tid < MAXR) g_bh[tid * NBLK2 + bid] = sh[tid];
}

// ---------------------------------------------------------------------------
// Sort pass 2: ONE block turns g_bh counts into exclusive base offsets.
// ---------------------------------------------------------------------------
__global__ __launch_bounds__(256) void k_scan() {
    __shared__ int rel_total[256];
    __shared__ int rel_base[256];
    __shared__ int sc[256];
    int t = threadIdx.x, warp = t >> 5, lane = t & 31;

    // phase 1: per-relation totals (warp-parallel row sums)
    for (int r = warp; r < MAXR; r += 8) {
        int s = 0;
        for (int j = lane; j < NBLK2; j += 32) s += g_bh[r * NBLK2 + j];
#pragma unroll
        for (int o = 16; o; o >>= 1) s += __shfl_xor_sync(~0u, s, o);
        if (lane == 0) rel_total[r] = s;
    }
    __syncthreads();

    // phase 2: exclusive scan of relation totals (Hillis-Steele over 256)
    int v = (t < MAXR) ? rel_total[t] : 0;
    sc[t] = v;
    __syncthreads();
    for (int off = 1; off < 256; off <<= 1) {
        int y = (t >= off) ? sc[t - off] : 0;
        __syncthreads();
        sc[t] += y;
        __syncthreads();
    }
    if (t < MAXR) rel_base[t] = sc[t] - v;
    __syncthreads();

    // phase 3: per-relation exclusive scans over blocks, carried shfl scans
    for (int r = warp; r < MAXR; r += 8) {
        int carry = rel_base[r];
        for (int base = 0; base < NBLK2; base += 32) {
            int j = base + lane;
            int val = (j < NBLK2) ? g_bh[r * NBLK2 + j] : 0;
            int inc = val;
#pragma unroll
            for (int o = 1; o < 32; o <<= 1) {
                int y = __shfl_up_sync(~0u, inc, o);
                if (lane >= o) inc += y;
            }
            if (j < NBLK2) g_bh[r * NBLK2 + j] = carry + inc - val;
            carry += __shfl_sync(~0u, inc, 31);
        }
    }
}

// ---------------------------------------------------------------------------
// Sort pass 3: scatter with shared cursors (no global atomics)
// ---------------------------------------------------------------------------
__global__ __launch_bounds__(SORT_TPB) void k_scatter(const int* __restrict__ src,
                                                      const int* __restrict__ dst,
                                                      const int* __restrict__ et,
                                                      const float* __restrict__ norm,
                                                      int n, int chunk) {
    __shared__ int cur[MAXR];
    int tid = threadIdx.x, bid = blockIdx.x;
    if (tid < MAXR) cur[tid] = g_bh[tid * NBLK2 + bid];
    __syncthreads();
    int lo = bid * chunk;
    int hi = lo + chunk; if (hi > n) hi = n;
    for (int e = lo + tid; e < hi; e += SORT_TPB) {
        int t = et[e];
        int d = dst[e];
        int s = src[e];
        float nv = __ldg(norm + d);
        int pos = atomicAdd(&cur[t], 1);
        int4 ed;
        ed.x = s;
        ed.y = d;
        ed.z = t;
        ed.w = __float_as_int(nv);
        g_edges[pos] = ed;
    }
}

// ---------------------------------------------------------------------------
// Edge kernel (R3 proven form, EPW=16): warp processes EPW consecutive
// etype-sorted edges; W cached in registers; RED.v4 directly into d_out
// (which holds zeros at this point).
//   lane l: basis block b = l>>1, output offset o0 = (l&1)*4
// ---------------------------------------------------------------------------
__global__ __launch_bounds__(256) void edge_kernel(
        const float* __restrict__ h,
        const float* __restrict__ weight,
        float* __restrict__ out,
        int nedges) {
    int gw   = (blockIdx.x * blockDim.x + threadIdx.x) >> 5;
    int lane = threadIdx.x & 31;
    int e0 = gw * EPW;
    if (e0 >= nedges) return;            // warp-uniform

    int b  = lane >> 1;
    int o0 = (lane & 1) * 4;

    int t_cur = -1;
    float4 w[SI];

    int e_end = e0 + EPW;
    if (e_end > nedges) e_end = nedges;

    for (int e = e0; e < e_end; e++) {
        int4 ed = g_edges[e];                 // warp-uniform broadcast load
        int s = ed.x, d = ed.y, t = ed.z;
        float nrm = __int_as_float(ed.w);

        if (t != t_cur) {                     // warp-uniform branch (rare)
            t_cur = t;
            const float* wb = weight + (size_t)t * W_PER_REL + b * (SI * SO) + o0;
#pragma unroll
            for (int i = 0; i < SI; i++)
                w[i] = __ldg(reinterpret_cast<const float4*>(wb + i * SO));
        }

        const float4* xp = reinterpret_cast<const float4*>(h + (size_t)s * IN_FEAT + b * SI);
        float4 xa = __ldg(xp);
        float4 xb = __ldg(xp + 1);
        float x[8] = {xa.x, xa.y, xa.z, xa.w, xb.x, xb.y, xb.z, xb.w};

        float4 acc = make_float4(0.f, 0.f, 0.f, 0.f);
#pragma unroll
        for (int i = 0; i < SI; i++) {
            acc.x = fmaf(x[i], w[i].x, acc.x);
            acc.y = fmaf(x[i], w[i].y, acc.y);
            acc.z = fmaf(x[i], w[i].z, acc.z);
            acc.w = fmaf(x[i], w[i].w, acc.w);
        }

        acc.x *= nrm; acc.y *= nrm; acc.z *= nrm; acc.w *= nrm;
        red_add_v4(out + (size_t)d * OUT_FEAT + lane * 4, acc);
    }
}

// ---------------------------------------------------------------------------
// GEMM + add + ReLU (runs LAST): out = relu(h @ lw + out)
// 64 rows x 128 cols per block, 256 threads -> thread = 8 rows x 4 cols.
// k-loop vectorized by 4: 4 LDG.128 (w) + 8 broadcast LDS.128 (x) + 128 FMA.
// ---------------------------------------------------------------------------
__global__ __launch_bounds__(256) void gemm_add_relu_kernel(
        const float* __restrict__ h,
        const float* __restrict__ lw,
        float* __restrict__ out) {
    __shared__ float4 xs[GM_ROWS][32];   // 32KB tile of h
    int r0 = blockIdx.x * GM_ROWS;
    int tid = threadIdx.x;

    const float4* h4 = reinterpret_cast<const float4*>(h);
    for (int idx = tid; idx < GM_ROWS * 32; idx += 256) {
        int r = idx >> 5, c = idx & 31;
        int gr = r0 + r;
        xs[r][c] = (gr < N_NODES) ? __ldg(&h4[(size_t)gr * 32 + c])
                                  : make_float4(0.f, 0.f, 0.f, 0.f);
    }
    __syncthreads();

    int cx = tid & 31;          // float4 col index (cols 4cx..4cx+3)
    int rg = (tid >> 5) * 8;    // row base within tile

    float4 acc[8];
#pragma unroll
    for (int r = 0; r < 8; r++) acc[r] = make_float4(0.f, 0.f, 0.f, 0.f);

    const float4* lw4 = reinterpret_cast<const float4*>(lw);

    for (int k4 = 0; k4 < 32; k4++) {        // 4 k-values per iteration
        float4 w0 = __ldg(&lw4[(size_t)(k4 * 4 + 0) * 32 + cx]);
        float4 w1 = __ldg(&lw4[(size_t)(k4 * 4 + 1) * 32 + cx]);
        float4 w2 = __ldg(&lw4[(size_t)(k4 * 4 + 2) * 32 + cx]);
        float4 w3 = __ldg(&lw4[(size_t)(k4 * 4 + 3) * 32 + cx]);
#pragma unroll
        for (int r = 0; r < 8; r++) {
            float4 xv = xs[rg + r][k4];      // warp-broadcast LDS.128
            acc[r].x = fmaf(xv.x, w0.x, acc[r].x);
            acc[r].y = fmaf(xv.x, w0.y, acc[r].y);
            acc[r].z = fmaf(xv.x, w0.z, acc[r].z);
            acc[r].w = fmaf(xv.x, w0.w, acc[r].w);
            acc[r].x = fmaf(xv.y, w1.x, acc[r].x);
            acc[r].y = fmaf(xv.y, w1.y, acc[r].y);
            acc[r].z = fmaf(xv.y, w1.z, acc[r].z);
            acc[r].w = fmaf(xv.y, w1.w, acc[r].w);
            acc[r].x = fmaf(xv.z, w2.x, acc[r].x);
            acc[r].y = fmaf(xv.z, w2.y, acc[r].y);
            acc[r].z = fmaf(xv.z, w2.z, acc[r].z);
            acc[r].w = fmaf(xv.z, w2.w, acc[r].w);
            acc[r].x = fmaf(xv.w, w3.x, acc[r].x);
            acc[r].y = fmaf(xv.w, w3.y, acc[r].y);
            acc[r].z = fmaf(xv.w, w3.z, acc[r].z);
            acc[r].w = fmaf(xv.w, w3.w, acc[r].w);
        }
    }

    float4* out4 = reinterpret_cast<float4*>(out);
#pragma unroll
    for (int r = 0; r < 8; r++) {
        int gr = r0 + rg + r;
        if (gr < N_NODES) {
            size_t idx = (size_t)gr * 32 + cx;
            float4 agg = out4[idx];           // edge aggregation (norm-scaled)
            float4 v;
            v.x = fmaxf(acc[r].x + agg.x, 0.f);
            v.y = fmaxf(acc[r].y + agg.y, 0.f);
            v.z = fmaxf(acc[r].z + agg.z, 0.f);
            v.w = fmaxf(acc[r].w + agg.w, 0.f);
            out4[idx] = v;
        }
    }
}

// ---------------------------------------------------------------------------
// Launch: hist(+zero out) -> scan -> scatter -> edge(RED into out)
//         -> gemm+add+relu (last)
// Inputs (metadata order): h, norm, weight, loop_weight, src, dst, etype
// ---------------------------------------------------------------------------
extern "C" void kernel_launch(void* const* d_in, const int* in_sizes, int n_in,
                              void* d_out, int out_size) {
    const float* h      = (const float*)d_in[0];
    const float* norm   = (const float*)d_in[1];
    const float* weight = (const float*)d_in[2];
    const float* lw     = (const float*)d_in[3];
    const int*   src    = (const int*)d_in[4];
    const int*   dst    = (const int*)d_in[5];
    const int*   etype  = (const int*)d_in[6];
    float* out = (float*)d_out;

    int nedges = in_sizes[4];
    if (nedges > E_MAX) nedges = E_MAX;
    int chunk = (nedges + NBLK2 - 1) / NBLK2;

    // ---- counting sort by etype (hist also zeroes d_out) ----
    k_hist<<<NBLK2, SORT_TPB>>>(etype, out, nedges, chunk);
    k_scan<<<1, 256>>>();
    k_scatter<<<NBLK2, SORT_TPB>>>(src, dst, etype, norm, nedges, chunk);

    // ---- per-edge messages, RED directly into d_out ----
    {
        int nwarps = (nedges + EPW - 1) / EPW;
        int blocks = (nwarps + 7) / 8;       // 8 warps / block
        edge_kernel<<<blocks, 256>>>(h, weight, out, nedges);
    }

    // ---- self-loop GEMM + add + ReLU (final pass) ----
    gemm_add_relu_kernel<<<(N_NODES + GM_ROWS - 1) / GM_ROWS, 256>>>(h, lw, out);
}

// round 13
// speedup vs baseline: 1.3789x; 1.3789x over previous
#include <cuda_runtime.h>
#include <cstdint>

#define N_NODES   50000
#define IN_FEAT   128
#define OUT_FEAT  128
#define NB        16
#define SI        8
#define SO        8
#define W_PER_REL (NB * SI * SO)   // 1024
#define E_MAX     500000
#define MAXR      200
#define NBLK2     232               // one wave of fat sort blocks
#define SORT_TPB  256
#define EPW       8                 // edges per warp in edge kernel
#define GM_ROWS   64

// Scratch (static device globals — allocation-free per harness rules)
__device__ int4 g_edges[E_MAX];            // (src, dst, etype, norm_bits), etype-sorted
__device__ int  g_bh[MAXR * NBLK2];        // per-(rel, block) counts -> base offsets
__device__ int  g_rel_total[MAXR];
__device__ int  g_rel_base[MAXR];

// ---------------------------------------------------------------------------
__device__ __forceinline__ void red_add_v4(float* addr, float4 v) {
    asm volatile("red.global.add.v4.f32 [%0], {%1, %2, %3, %4};"
                 :: "l"(addr), "f"(v.x), "f"(v.y), "f"(v.z), "f"(v.w)
                 : "memory");
}

// ---------------------------------------------------------------------------
// Sort pass 1: per-block histogram over contiguous edge chunk (grid = NBLK2)
// ---------------------------------------------------------------------------
__global__ __launch_bounds__(SORT_TPB) void k_hist(const int* __restrict__ et,
                                                   int n, int chunk) {
    __shared__ int sh[MAXR];
    int tid = threadIdx.x, bid = blockIdx.x;
    if (tid < MAXR) sh[tid] = 0;
    __syncthreads();
    int lo = bid * chunk;
    int hi = lo + chunk; if (hi > n) hi = n;
    for (int e = lo + tid; e < hi; e += SORT_TPB)
        atomicAdd(&sh[et[e]], 1);
    __syncthreads();
    if (tid < MAXR) g_bh[tid * NBLK2 + bid] = sh[tid];
}

// ---------------------------------------------------------------------------
// Sort pass 2a: per-relation totals (grid = MAXR, 256 thr; 232 entries each)
// ---------------------------------------------------------------------------
__global__ __launch_bounds__(256) void k_rowsum() {
    __shared__ int sh[256];
    int r = blockIdx.x, tid = threadIdx.x;
    int s = (tid < NBLK2) ? g_bh[r * NBLK2 + tid] : 0;
    sh[tid] = s;
    __syncthreads();
    for (int off = 128; off > 0; off >>= 1) {
        if (tid < off) sh[tid] += sh[tid + off];
        __syncthreads();
    }
    if (tid == 0) g_rel_total[r] = sh[0];
}

// ---------------------------------------------------------------------------
// Sort pass 2b: exclusive scan over relations (1 block, 256 thr)
// ---------------------------------------------------------------------------
__global__ __launch_bounds__(256) void k_relscan() {
    __shared__ int sh[256];
    int t = threadIdx.x;
    int v = (t < MAXR) ? g_rel_total[t] : 0;
    sh[t] = v;
    __syncthreads();
    for (int off = 1; off < 256; off <<= 1) {
        int x = (t >= off) ? sh[t - off] : 0;
        __syncthreads();
        sh[t] += x;
        __syncthreads();
    }
    if (t < MAXR) g_rel_base[t] = sh[t] - v;
}

// ---------------------------------------------------------------------------
// Sort pass 2c: per-relation exclusive scan over 232 blocks, in place
// (grid = MAXR; single 256-wide Hillis-Steele chunk — no serial loop)
// ---------------------------------------------------------------------------
__global__ __launch_bounds__(256) void k_rowscan() {
    __shared__ int sh[256];
    int r = blockIdx.x, tid = threadIdx.x;
    int base = g_rel_base[r];
    int v = (tid < NBLK2) ? g_bh[r * NBLK2 + tid] : 0;
    sh[tid] = v;
    __syncthreads();
    for (int off = 1; off < 256; off <<= 1) {
        int x = (tid >= off) ? sh[tid - off] : 0;
        __syncthreads();
        sh[tid] += x;
        __syncthreads();
    }
    if (tid < NBLK2) g_bh[r * NBLK2 + tid] = base + sh[tid] - v;  // exclusive
}

// ---------------------------------------------------------------------------
// Sort pass 3: scatter with shared cursors (no global atomics)
// ---------------------------------------------------------------------------
__global__ __launch_bounds__(SORT_TPB) void k_scatter(const int* __restrict__ src,
                                                      const int* __restrict__ dst,
                                                      const int* __restrict__ et,
                                                      const float* __restrict__ norm,
                                                      int n, int chunk) {
    __shared__ int cur[MAXR];
    int tid = threadIdx.x, bid = blockIdx.x;
    if (tid < MAXR) cur[tid] = g_bh[tid * NBLK2 + bid];
    __syncthreads();
    int lo = bid * chunk;
    int hi = lo + chunk; if (hi > n) hi = n;
    for (int e = lo + tid; e < hi; e += SORT_TPB) {
        int t = et[e];
        int d = dst[e];
        int s = src[e];
        float nv = __ldg(norm + d);
        int pos = atomicAdd(&cur[t], 1);
        int4 ed;
        ed.x = s;
        ed.y = d;
        ed.z = t;
        ed.w = __float_as_int(nv);
        g_edges[pos] = ed;
    }
}

// ---------------------------------------------------------------------------
// Kernel A (R7 measured-best): d_out = h @ loop_weight
// 64 rows x 128 cols per block, 256 threads -> thread = 8 rows x 4 cols.
// k-loop vectorized by 4: 4 LDG.128 (w) + 8 broadcast LDS.128 (x) + 128 FMA.
// ---------------------------------------------------------------------------
__global__ __launch_bounds__(256) void loop_gemm_kernel(
        const float* __restrict__ h,
        const float* __restrict__ lw,
        float* __restrict__ out) {
    __shared__ float4 xs[GM_ROWS][32];   // 32KB tile of h
    int r0 = blockIdx.x * GM_ROWS;
    int tid = threadIdx.x;

    const float4* h4 = reinterpret_cast<const float4*>(h);
    for (int idx = tid; idx < GM_ROWS * 32; idx += 256) {
        int r = idx >> 5, c = idx & 31;
        int gr = r0 + r;
        xs[r][c] = (gr < N_NODES) ? __ldg(&h4[(size_t)gr * 32 + c])
                                  : make_float4(0.f, 0.f, 0.f, 0.f);
    }
    __syncthreads();

    int cx = tid & 31;          // float4 col index (cols 4cx..4cx+3)
    int rg = (tid >> 5) * 8;    // row base within tile

    float4 acc[8];
#pragma unroll
    for (int r = 0; r < 8; r++) acc[r] = make_float4(0.f, 0.f, 0.f, 0.f);

    const float4* lw4 = reinterpret_cast<const float4*>(lw);

    for (int k4 = 0; k4 < 32; k4++) {        // 4 k-values per iteration
        float4 w0 = __ldg(&lw4[(size_t)(k4 * 4 + 0) * 32 + cx]);
        float4 w1 = __ldg(&lw4[(size_t)(k4 * 4 + 1) * 32 + cx]);
        float4 w2 = __ldg(&lw4[(size_t)(k4 * 4 + 2) * 32 + cx]);
        float4 w3 = __ldg(&lw4[(size_t)(k4 * 4 + 3) * 32 + cx]);
#pragma unroll
        for (int r = 0; r < 8; r++) {
            float4 xv = xs[rg + r][k4];      // warp-broadcast LDS.128
            acc[r].x = fmaf(xv.x, w0.x, acc[r].x);
            acc[r].y = fmaf(xv.x, w0.y, acc[r].y);
            acc[r].z = fmaf(xv.x, w0.z, acc[r].z);
            acc[r].w = fmaf(xv.x, w0.w, acc[r].w);
            acc[r].x = fmaf(xv.y, w1.x, acc[r].x);
            acc[r].y = fmaf(xv.y, w1.y, acc[r].y);
            acc[r].z = fmaf(xv.y, w1.z, acc[r].z);
            acc[r].w = fmaf(xv.y, w1.w, acc[r].w);
            acc[r].x = fmaf(xv.z, w2.x, acc[r].x);
            acc[r].y = fmaf(xv.z, w2.y, acc[r].y);
            acc[r].z = fmaf(xv.z, w2.z, acc[r].z);
            acc[r].w = fmaf(xv.z, w2.w, acc[r].w);
            acc[r].x = fmaf(xv.w, w3.x, acc[r].x);
            acc[r].y = fmaf(xv.w, w3.y, acc[r].y);
            acc[r].z = fmaf(xv.w, w3.z, acc[r].z);
            acc[r].w = fmaf(xv.w, w3.w, acc[r].w);
        }
    }

    float4* out4 = reinterpret_cast<float4*>(out);
#pragma unroll
    for (int r = 0; r < 8; r++) {
        int gr = r0 + rg + r;
        if (gr < N_NODES) out4[(size_t)gr * 32 + cx] = acc[r];
    }
}

// ---------------------------------------------------------------------------
// Kernel B (exact R3 champion form, EPW=8): warp processes EPW consecutive
// etype-sorted edges; W cached in registers; RED.v4 into d_out.
//   lane l: basis block b = l>>1, output offset o0 = (l&1)*4
// ---------------------------------------------------------------------------
__global__ __launch_bounds__(256) void edge_kernel(
        const float* __restrict__ h,
        const float* __restrict__ weight,
        float* __restrict__ out,
        int nedges) {
    int gw   = (blockIdx.x * blockDim.x + threadIdx.x) >> 5;
    int lane = threadIdx.x & 31;
    int e0 = gw * EPW;
    if (e0 >= nedges) return;            // warp-uniform

    int b  = lane >> 1;
    int o0 = (lane & 1) * 4;

    int t_cur = -1;
    float4 w[SI];

    int e_end = e0 + EPW;
    if (e_end > nedges) e_end = nedges;

    for (int e = e0; e < e_end; e++) {
        int4 ed = g_edges[e];                 // warp-uniform broadcast load
        int s = ed.x, d = ed.y, t = ed.z;
        float nrm = __int_as_float(ed.w);

        if (t != t_cur) {                     // warp-uniform branch (rare)
            t_cur = t;
            const float* wb = weight + (size_t)t * W_PER_REL + b * (SI * SO) + o0;
#pragma unroll
            for (int i = 0; i < SI; i++)
                w[i] = __ldg(reinterpret_cast<const float4*>(wb + i * SO));
        }

        const float4* xp = reinterpret_cast<const float4*>(h + (size_t)s * IN_FEAT + b * SI);
        float4 xa = __ldg(xp);
        float4 xb = __ldg(xp + 1);
        float x[8] = {xa.x, xa.y, xa.z, xa.w, xb.x, xb.y, xb.z, xb.w};

        float4 acc = make_float4(0.f, 0.f, 0.f, 0.f);
#pragma unroll
        for (int i = 0; i < SI; i++) {
            acc.x = fmaf(x[i], w[i].x, acc.x);
            acc.y = fmaf(x[i], w[i].y, acc.y);
            acc.z = fmaf(x[i], w[i].z, acc.z);
            acc.w = fmaf(x[i], w[i].w, acc.w);
        }

        acc.x *= nrm; acc.y *= nrm; acc.z *= nrm; acc.w *= nrm;
        red_add_v4(out + (size_t)d * OUT_FEAT + lane * 4, acc);
    }
}

// ---------------------------------------------------------------------------
// Kernel C: in-place ReLU (float4 vectorized)
// ---------------------------------------------------------------------------
__global__ void relu_kernel(float4* __restrict__ out, int n4) {
    int i = blockIdx.x * blockDim.x + threadIdx.x;
    if (i >= n4) return;
    float4 v = out[i];
    v.x = fmaxf(v.x, 0.f);
    v.y = fmaxf(v.y, 0.f);
    v.z = fmaxf(v.z, 0.f);
    v.w = fmaxf(v.w, 0.f);
    out[i] = v;
}

// ---------------------------------------------------------------------------
// Launch: 5-kernel parallel sort -> GEMM init -> edge scatter -> ReLU
// Inputs (metadata order): h, norm, weight, loop_weight, src, dst, etype
// ---------------------------------------------------------------------------
extern "C" void kernel_launch(void* const* d_in, const int* in_sizes, int n_in,
                              void* d_out, int out_size) {
    const float* h      = (const float*)d_in[0];
    const float* norm   = (const float*)d_in[1];
    const float* weight = (const float*)d_in[2];
    const float* lw     = (const float*)d_in[3];
    const int*   src    = (const int*)d_in[4];
    const int*   dst    = (const int*)d_in[5];
    const int*   etype  = (const int*)d_in[6];
    float* out = (float*)d_out;

    int nedges = in_sizes[4];
    if (nedges > E_MAX) nedges = E_MAX;
    int chunk = (nedges + NBLK2 - 1) / NBLK2;

    // ---- contention-free counting sort by etype (all scans multi-block) ----
    k_hist<<<NBLK2, SORT_TPB>>>(etype, nedges, chunk);
    k_rowsum<<<MAXR, 256>>>();
    k_relscan<<<1, 256>>>();
    k_rowscan<<<MAXR, 256>>>();
    k_scatter<<<NBLK2, SORT_TPB>>>(src, dst, etype, norm, nedges, chunk);

    // ---- self-loop GEMM (initializes d_out) ----
    loop_gemm_kernel<<<(N_NODES + GM_ROWS - 1) / GM_ROWS, 256>>>(h, lw, out);

    // ---- per-edge messages (W cached in registers across EPW edges) ----
    {
        int nwarps = (nedges + EPW - 1) / EPW;
        int blocks = (nwarps + 7) / 8;       // 8 warps / block
        edge_kernel<<<blocks, 256>>>(h, weight, out, nedges);
    }

    // ---- ReLU ----
    {
        int n4 = N_NODES * OUT_FEAT / 4;
        relu_kernel<<<(n4 + 255) / 256, 256>>>((float4*)out, n4);
    }
}

// round 14
// speedup vs baseline: 1.4158x; 1.0268x over previous
#include <cuda_runtime.h>
#include <cstdint>

#define N_NODES   50000
#define IN_FEAT   128
#define OUT_FEAT  128
#define NB        16
#define SI        8
#define SO        8
#define W_PER_REL (NB * SI * SO)   // 1024
#define E_MAX     500000
#define MAXR      200
#define NBLK2     232               // one wave of fat sort blocks
#define SORT_TPB  256
#define EPW       8                 // edges per warp in edge kernel
#define GM_ROWS   64

// Scratch (static device globals — allocation-free per harness rules)
__device__ int4 g_edges[E_MAX];            // (src, dst, etype, norm_bits), etype-sorted
__device__ int  g_bh[MAXR * NBLK2];        // per-(rel, block) counts -> base offsets
__device__ int  g_rel_total[MAXR];
__device__ int  g_rel_base[MAXR];

// ---------------------------------------------------------------------------
__device__ __forceinline__ void red_add_v4(float* addr, float4 v) {
    asm volatile("red.global.add.v4.f32 [%0], {%1, %2, %3, %4};"
                 :: "l"(addr), "f"(v.x), "f"(v.y), "f"(v.z), "f"(v.w)
                 : "memory");
}

// Packed 2xfp32 FMA (sm_100a): d = a*b + d, two lanes per instruction
__device__ __forceinline__ uint64_t pack2(float lo, float hi) {
    uint64_t r;
    asm("mov.b64 %0, {%1, %2};" : "=l"(r) : "f"(lo), "f"(hi));
    return r;
}
__device__ __forceinline__ void unpack2(uint64_t v, float& lo, float& hi) {
    asm("mov.b64 {%0, %1}, %2;" : "=f"(lo), "=f"(hi) : "l"(v));
}
__device__ __forceinline__ void ffma2(uint64_t& d, uint64_t a, uint64_t b) {
    asm("fma.rn.f32x2 %0, %1, %2, %0;" : "+l"(d) : "l"(a), "l"(b));
}

// ---------------------------------------------------------------------------
// Sort pass 1: per-block histogram over contiguous edge chunk (grid = NBLK2)
// ---------------------------------------------------------------------------
__global__ __launch_bounds__(SORT_TPB) void k_hist(const int* __restrict__ et,
                                                   int n, int chunk) {
    __shared__ int sh[MAXR];
    int tid = threadIdx.x, bid = blockIdx.x;
    if (tid < MAXR) sh[tid] = 0;
    __syncthreads();
    int lo = bid * chunk;
    int hi = lo + chunk; if (hi > n) hi = n;
    for (int e = lo + tid; e < hi; e += SORT_TPB)
        atomicAdd(&sh[et[e]], 1);
    __syncthreads();
    if (tid < MAXR) g_bh[tid * NBLK2 + bid] = sh[tid];
}

// ---------------------------------------------------------------------------
// Sort pass 2a: per-relation totals (grid = MAXR, 256 thr; 232 entries each)
// ---------------------------------------------------------------------------
__global__ __launch_bounds__(256) void k_rowsum() {
    __shared__ int sh[256];
    int r = blockIdx.x, tid = threadIdx.x;
    int s = (tid < NBLK2) ? g_bh[r * NBLK2 + tid] : 0;
    sh[tid] = s;
    __syncthreads();
    for (int off = 128; off > 0; off >>= 1) {
        if (tid < off) sh[tid] += sh[tid + off];
        __syncthreads();
    }
    if (tid == 0) g_rel_total[r] = sh[0];
}

// ---------------------------------------------------------------------------
// Sort pass 2b: exclusive scan over relations (1 block, 256 thr)
// ---------------------------------------------------------------------------
__global__ __launch_bounds__(256) void k_relscan() {
    __shared__ int sh[256];
    int t = threadIdx.x;
    int v = (t < MAXR) ? g_rel_total[t] : 0;
    sh[t] = v;
    __syncthreads();
    for (int off = 1; off < 256; off <<= 1) {
        int x = (t >= off) ? sh[t - off] : 0;
        __syncthreads();
        sh[t] += x;
        __syncthreads();
    }
    if (t < MAXR) g_rel_base[t] = sh[t] - v;
}

// ---------------------------------------------------------------------------
// Sort pass 2c: per-relation exclusive scan over 232 blocks, in place
// (grid = MAXR; single 256-wide Hillis-Steele chunk)
// ---------------------------------------------------------------------------
__global__ __launch_bounds__(256) void k_rowscan() {
    __shared__ int sh[256];
    int r = blockIdx.x, tid = threadIdx.x;
    int base = g_rel_base[r];
    int v = (tid < NBLK2) ? g_bh[r * NBLK2 + tid] : 0;
    sh[tid] = v;
    __syncthreads();
    for (int off = 1; off < 256; off <<= 1) {
        int x = (tid >= off) ? sh[tid - off] : 0;
        __syncthreads();
        sh[tid] += x;
        __syncthreads();
    }
    if (tid < NBLK2) g_bh[r * NBLK2 + tid] = base + sh[tid] - v;  // exclusive
}

// ---------------------------------------------------------------------------
// Sort pass 3: scatter with shared cursors (no global atomics)
// ---------------------------------------------------------------------------
__global__ __launch_bounds__(SORT_TPB) void k_scatter(const int* __restrict__ src,
                                                      const int* __restrict__ dst,
                                                      const int* __restrict__ et,
                                                      const float* __restrict__ norm,
                                                      int n, int chunk) {
    __shared__ int cur[MAXR];
    int tid = threadIdx.x, bid = blockIdx.x;
    if (tid < MAXR) cur[tid] = g_bh[tid * NBLK2 + bid];
    __syncthreads();
    int lo = bid * chunk;
    int hi = lo + chunk; if (hi > n) hi = n;
    for (int e = lo + tid; e < hi; e += SORT_TPB) {
        int t = et[e];
        int d = dst[e];
        int s = src[e];
        float nv = __ldg(norm + d);
        int pos = atomicAdd(&cur[t], 1);
        int4 ed;
        ed.x = s;
        ed.y = d;
        ed.z = t;
        ed.w = __float_as_int(nv);
        g_edges[pos] = ed;
    }
}

// ---------------------------------------------------------------------------
// Kernel A: d_out = h @ loop_weight  — packed f32x2 FMA version.
// 64 rows x 128 cols per block, 256 threads -> thread = 8 rows x 4 cols.
// Accumulators are f32x2 pairs: accA = cols {4cx,4cx+1}, accB = {4cx+2,4cx+3}.
// Per k4 iter: 4 LDG.128 (w) + 8 LDS.128 (x) + 8 w-packs + 32 x-packs
//              + 64 FFMA2  (vs 128 FFMA before — FMA-pipe floor halves).
// ---------------------------------------------------------------------------
__global__ __launch_bounds__(256) void loop_gemm_kernel(
        const float* __restrict__ h,
        const float* __restrict__ lw,
        float* __restrict__ out) {
    __shared__ float4 xs[GM_ROWS][32];   // 32KB tile of h
    int r0 = blockIdx.x * GM_ROWS;
    int tid = threadIdx.x;

    const float4* h4 = reinterpret_cast<const float4*>(h);
    for (int idx = tid; idx < GM_ROWS * 32; idx += 256) {
        int r = idx >> 5, c = idx & 31;
        int gr = r0 + r;
        xs[r][c] = (gr < N_NODES) ? __ldg(&h4[(size_t)gr * 32 + c])
                                  : make_float4(0.f, 0.f, 0.f, 0.f);
    }
    __syncthreads();

    int cx = tid & 31;          // float4 col index (cols 4cx..4cx+3)
    int rg = (tid >> 5) * 8;    // row base within tile

    uint64_t accA[8], accB[8];
#pragma unroll
    for (int r = 0; r < 8; r++) { accA[r] = 0ull; accB[r] = 0ull; }

    const float4* lw4 = reinterpret_cast<const float4*>(lw);

    for (int k4 = 0; k4 < 32; k4++) {        // 4 k-values per iteration
        float4 w0 = __ldg(&lw4[(size_t)(k4 * 4 + 0) * 32 + cx]);
        float4 w1 = __ldg(&lw4[(size_t)(k4 * 4 + 1) * 32 + cx]);
        float4 w2 = __ldg(&lw4[(size_t)(k4 * 4 + 2) * 32 + cx]);
        float4 w3 = __ldg(&lw4[(size_t)(k4 * 4 + 3) * 32 + cx]);
        uint64_t wA0 = pack2(w0.x, w0.y), wB0 = pack2(w0.z, w0.w);
        uint64_t wA1 = pack2(w1.x, w1.y), wB1 = pack2(w1.z, w1.w);
        uint64_t wA2 = pack2(w2.x, w2.y), wB2 = pack2(w2.z, w2.w);
        uint64_t wA3 = pack2(w3.x, w3.y), wB3 = pack2(w3.z, w3.w);
#pragma unroll
        for (int r = 0; r < 8; r++) {
            float4 xv = xs[rg + r][k4];      // warp-broadcast LDS.128
            uint64_t xx;
            xx = pack2(xv.x, xv.x); ffma2(accA[r], xx, wA0); ffma2(accB[r], xx, wB0);
            xx = pack2(xv.y, xv.y); ffma2(accA[r], xx, wA1); ffma2(accB[r], xx, wB1);
            xx = pack2(xv.z, xv.z); ffma2(accA[r], xx, wA2); ffma2(accB[r], xx, wB2);
            xx = pack2(xv.w, xv.w); ffma2(accA[r], xx, wA3); ffma2(accB[r], xx, wB3);
        }
    }

    float4* out4 = reinterpret_cast<float4*>(out);
#pragma unroll
    for (int r = 0; r < 8; r++) {
        int gr = r0 + rg + r;
        if (gr < N_NODES) {
            float4 v;
            unpack2(accA[r], v.x, v.y);
            unpack2(accB[r], v.z, v.w);
            out4[(size_t)gr * 32 + cx] = v;
        }
    }
}

// ---------------------------------------------------------------------------
// Kernel B (exact R3 champion form, EPW=8): warp processes EPW consecutive
// etype-sorted edges; W cached in registers; RED.v4 into d_out.
//   lane l: basis block b = l>>1, output offset o0 = (l&1)*4
// ---------------------------------------------------------------------------
__global__ __launch_bounds__(256) void edge_kernel(
        const float* __restrict__ h,
        const float* __restrict__ weight,
        float* __restrict__ out,
        int nedges) {
    int gw   = (blockIdx.x * blockDim.x + threadIdx.x) >> 5;
    int lane = threadIdx.x & 31;
    int e0 = gw * EPW;
    if (e0 >= nedges) return;            // warp-uniform

    int b  = lane >> 1;
    int o0 = (lane & 1) * 4;

    int t_cur = -1;
    float4 w[SI];

    int e_end = e0 + EPW;
    if (e_end > nedges) e_end = nedges;

    for (int e = e0; e < e_end; e++) {
        int4 ed = g_edges[e];                 // warp-uniform broadcast load
        int s = ed.x, d = ed.y, t = ed.z;
        float nrm = __int_as_float(ed.w);

        if (t != t_cur) {                     // warp-uniform branch (rare)
            t_cur = t;
            const float* wb = weight + (size_t)t * W_PER_REL + b * (SI * SO) + o0;
#pragma unroll
            for (int i = 0; i < SI; i++)
                w[i] = __ldg(reinterpret_cast<const float4*>(wb + i * SO));
        }

        const float4* xp = reinterpret_cast<const float4*>(h + (size_t)s * IN_FEAT + b * SI);
        float4 xa = __ldg(xp);
        float4 xb = __ldg(xp + 1);
        float x[8] = {xa.x, xa.y, xa.z, xa.w, xb.x, xb.y, xb.z, xb.w};

        float4 acc = make_float4(0.f, 0.f, 0.f, 0.f);
#pragma unroll
        for (int i = 0; i < SI; i++) {
            acc.x = fmaf(x[i], w[i].x, acc.x);
            acc.y = fmaf(x[i], w[i].y, acc.y);
            acc.z = fmaf(x[i], w[i].z, acc.z);
            acc.w = fmaf(x[i], w[i].w, acc.w);
        }

        acc.x *= nrm; acc.y *= nrm; acc.z *= nrm; acc.w *= nrm;
        red_add_v4(out + (size_t)d * OUT_FEAT + lane * 4, acc);
    }
}

// ---------------------------------------------------------------------------
// Kernel C: in-place ReLU (float4 vectorized)
// ---------------------------------------------------------------------------
__global__ void relu_kernel(float4* __restrict__ out, int n4) {
    int i = blockIdx.x * blockDim.x + threadIdx.x;
    if (i >= n4) return;
    float4 v = out[i];
    v.x = fmaxf(v.x, 0.f);
    v.y = fmaxf(v.y, 0.f);
    v.z = fmaxf(v.z, 0.f);
    v.w = fmaxf(v.w, 0.f);
    out[i] = v;
}

// ---------------------------------------------------------------------------
// Launch: 5-kernel parallel sort -> GEMM init -> edge scatter -> ReLU
// Inputs (metadata order): h, norm, weight, loop_weight, src, dst, etype
// ---------------------------------------------------------------------------
extern "C" void kernel_launch(void* const* d_in, const int* in_sizes, int n_in,
                              void* d_out, int out_size) {
    const float* h      = (const float*)d_in[0];
    const float* norm   = (const float*)d_in[1];
    const float* weight = (const float*)d_in[2];
    const float* lw     = (const float*)d_in[3];
    const int*   src    = (const int*)d_in[4];
    const int*   dst    = (const int*)d_in[5];
    const int*   etype  = (const int*)d_in[6];
    float* out = (float*)d_out;

    int nedges = in_sizes[4];
    if (nedges > E_MAX) nedges = E_MAX;
    int chunk = (nedges + NBLK2 - 1) / NBLK2;

    // ---- contention-free counting sort by etype (all scans multi-block) ----
    k_hist<<<NBLK2, SORT_TPB>>>(etype, nedges, chunk);
    k_rowsum<<<MAXR, 256>>>();
    k_relscan<<<1, 256>>>();
    k_rowscan<<<MAXR, 256>>>();
    k_scatter<<<NBLK2, SORT_TPB>>>(src, dst, etype, norm, nedges, chunk);

    // ---- self-loop GEMM (initializes d_out) ----
    loop_gemm_kernel<<<(N_NODES + GM_ROWS - 1) / GM_ROWS, 256>>>(h, lw, out);

    // ---- per-edge messages (W cached in registers across EPW edges) ----
    {
        int nwarps = (nedges + EPW - 1) / EPW;
        int blocks = (nwarps + 7) / 8;       // 8 warps / block
        edge_kernel<<<blocks, 256>>>(h, weight, out, nedges);
    }

    // ---- ReLU ----
    {
        int n4 = N_NODES * OUT_FEAT / 4;
        relu_kernel<<<(n4 + 255) / 256, 256>>>((float4*)out, n4);
    }
}